// round 8
// baseline (speedup 1.0000x reference)
// R8: pack rows instead of codes. z row-pairs come packed straight from
// LDS.128; e is pre-duplicated in memory (g_eTd) so (e,e) pairs also come
// straight from LDS.128 -> zero pack movs in the inner loop.
// Per-(row,code,d) arithmetic lane-identical to R7 (rel_err 0.0).
#include <cuda_runtime.h>
#include <cstdint>

#define BM 128
#define BK 128
#define DCH 8
#define D_DIM 256
#define K_CODES 1024
#define HW 1024
#define NCHUNK (D_DIM / DCH)     // 32
#define NKT (K_CODES / BK)       // 8
#define NST (NKT * NCHUNK)       // 256 pipeline stages

// Duplicated transposed codebook: g_eTd[d][2k] = g_eTd[d][2k+1] = e_k[d].
__device__ float g_eTd[D_DIM * 2 * K_CODES];   // 2 MB, L2-resident
__device__ float g_e2[K_CODES];                // ||e_k||^2

__global__ void vq_prep(const float* __restrict__ emb) {
    const int j = blockIdx.x;
    const int d = threadIdx.x;
    float v = emb[j * D_DIM + d];
    g_eTd[d * (2 * K_CODES) + 2 * j]     = v;
    g_eTd[d * (2 * K_CODES) + 2 * j + 1] = v;
    float s = __fmul_rn(v, v);
    #pragma unroll
    for (int o = 16; o > 0; o >>= 1)
        s = __fadd_rn(s, __shfl_down_sync(0xFFFFFFFFu, s, o));
    __shared__ float ws[8];
    if ((d & 31) == 0) ws[d >> 5] = s;
    __syncthreads();
    if (d == 0) {
        float t = ws[0];
        #pragma unroll
        for (int w = 1; w < 8; w++) t = __fadd_rn(t, ws[w]);
        g_e2[j] = t;
    }
}

__device__ __forceinline__ void cp_async16_ca(uint32_t dst, const void* src) {
    asm volatile("cp.async.ca.shared.global [%0], [%1], 16;\n" :: "r"(dst), "l"(src));
}
__device__ __forceinline__ void cp_async16_cg(uint32_t dst, const void* src) {
    asm volatile("cp.async.cg.shared.global [%0], [%1], 16;\n" :: "r"(dst), "l"(src));
}
__device__ __forceinline__ void cp_commit() {
    asm volatile("cp.async.commit_group;\n" ::: "memory");
}
__device__ __forceinline__ void cp_wait0() {
    asm volatile("cp.async.wait_group 0;\n" ::: "memory");
}

// Packed f32x2: each lane is a standard rn fp32 FMA — bit-identical to
// __fmaf_rn, exactness preserved.
__device__ __forceinline__ void unpack2(unsigned long long v, float& lo, float& hi) {
    asm("mov.b64 {%0, %1}, %2;" : "=f"(lo), "=f"(hi) : "l"(v));
}
__device__ __forceinline__ unsigned long long fma2(unsigned long long a,
                                                   unsigned long long b,
                                                   unsigned long long c) {
    unsigned long long d;
    asm("fma.rn.f32x2 %0, %1, %2, %3;" : "=l"(d) : "l"(a), "l"(b), "l"(c));
    return d;
}

__global__ void __launch_bounds__(256, 2) vq_main(
    const float* __restrict__ z, const float* __restrict__ emb,
    float* __restrict__ zq, float* __restrict__ idxf, float* __restrict__ loss)
{
    __shared__ float zs[2][DCH][BM];            // 8 KB
    __shared__ float es[2][DCH][2 * BK];        // 16 KB (duplicated codes)
    __shared__ float szs[BM];
    __shared__ unsigned long long rmin[BM];

    const int tid = threadIdx.x;
    const int tx = tid & 15;
    const int ty = tid >> 4;
    const int nbase = blockIdx.x * BM;
    const int b = nbase / HW;
    const int hwbase = nbase % HW;
    const float* zb = z + (size_t)b * (D_DIM * HW) + hwbase;

    // Loaders: zs = 4 KB/stage (1 cp/thread), es = 8 KB/stage (2 cp/thread).
    const int lr = tid >> 5;                    // 0..7 (d within chunk)
    const int lcz = (tid & 31) << 2;            // zs float col 0..124
    const int lce = (tid & 31) << 2;            // es float4-pair base

    const uint32_t zs_smem = (uint32_t)__cvta_generic_to_shared(&zs[0][0][0]);
    const uint32_t es_smem = (uint32_t)__cvta_generic_to_shared(&es[0][0][0]);

    // Stage 0 load overlaps the ||z||^2 pass.
    {
        cp_async16_ca(zs_smem + (lr * BM + lcz) * 4, &zb[(size_t)lr * HW + lcz]);
        cp_async16_cg(es_smem + (lr * 2 * BK + lce) * 4,
                      &g_eTd[lr * (2 * K_CODES) + lce]);
        cp_async16_cg(es_smem + (lr * 2 * BK + lce + 128) * 4,
                      &g_eTd[lr * (2 * K_CODES) + lce + 128]);
        cp_commit();
    }

    // Per-row ||z||^2: sequential over d, rounded squares (exactness-critical).
    if (tid < BM) {
        rmin[tid] = ~0ULL;
        float s = 0.f;
        const float* zp = zb + tid;
        for (int d = 0; d < D_DIM; d++) {
            float v = zp[(size_t)d * HW];
            s = __fadd_rn(s, __fmul_rn(v, v));
        }
        szs[tid] = s;
    }
    __syncthreads();

    float minv[8];
    unsigned minj[8];
    #pragma unroll
    for (int i = 0; i < 8; i++) { minv[i] = 3.402823466e38f; minj[i] = 0u; }

    unsigned long long acc2[4][8];              // [row-pair][code]

    for (int s = 0; s < NST; s++) {
        const int buf = s & 1;
        const int chunk = s & (NCHUNK - 1);
        const int kt = (s >> 5) * BK;

        cp_wait0();
        __syncthreads();

        if (s + 1 < NST) {
            const int nb = (s + 1) & 1;
            const int nd0 = ((s + 1) & (NCHUNK - 1)) * DCH;
            const int nkt = ((s + 1) >> 5) * BK;
            cp_async16_ca(zs_smem + ((nb * DCH + lr) * BM + lcz) * 4,
                          &zb[(size_t)(nd0 + lr) * HW + lcz]);
            cp_async16_cg(es_smem + ((nb * DCH + lr) * 2 * BK + lce) * 4,
                          &g_eTd[(size_t)(nd0 + lr) * (2 * K_CODES) + nkt * 2 + lce]);
            cp_async16_cg(es_smem + ((nb * DCH + lr) * 2 * BK + lce + 128) * 4,
                          &g_eTd[(size_t)(nd0 + lr) * (2 * K_CODES) + nkt * 2 + lce + 128]);
            cp_commit();
        }

        if (chunk == 0) {
            #pragma unroll
            for (int i = 0; i < 4; i++)
                #pragma unroll
                for (int j = 0; j < 8; j++) acc2[i][j] = 0ULL;
        }

        #pragma unroll
        for (int dd = 0; dd < DCH; dd++) {
            // Row pairs straight from LDS.128 (broadcast, conflict-free).
            const ulonglong2* zp = (const ulonglong2*)&zs[buf][dd][ty * 8];
            ulonglong2 zA = zp[0], zB = zp[1];
            unsigned long long zpair[4] = {zA.x, zA.y, zB.x, zB.y};
            // Duplicated (e,e) pairs straight from LDS.128 (contiguous 256B).
            const ulonglong2* ed = (const ulonglong2*)&es[buf][dd][0];
            ulonglong2 e0 = ed[tx], e1 = ed[tx + 16], e2v = ed[tx + 32], e3 = ed[tx + 48];
            unsigned long long eg[8] = {e0.x, e0.y, e1.x, e1.y,
                                        e2v.x, e2v.y, e3.x, e3.y};
            #pragma unroll
            for (int rp = 0; rp < 4; rp++)
                #pragma unroll
                for (int c = 0; c < 8; c++)
                    acc2[rp][c] = fma2(zpair[rp], eg[c], acc2[rp][c]);
        }

        if (chunk == NCHUNK - 1) {
            // Codes per thread: 2tx + 32g + h, ascending in (g, h) — same
            // mapping and strict-< first-index tie-break as R7.
            #pragma unroll
            for (int g = 0; g < 4; g++) {
                const int code0 = kt + 2 * tx + 32 * g;
                const float e2a = g_e2[code0];
                const float e2b = g_e2[code0 + 1];
                #pragma unroll
                for (int rp = 0; rp < 4; rp++) {
                    const float sz0 = szs[ty * 8 + 2 * rp];
                    const float sz1 = szs[ty * 8 + 2 * rp + 1];
                    float dA0, dA1, dB0, dB1;
                    unpack2(acc2[rp][2 * g],     dA0, dA1);   // code0: rows 2rp,2rp+1
                    unpack2(acc2[rp][2 * g + 1], dB0, dB1);   // code0+1
                    // row 2rp
                    float t = __fadd_rn(sz0, e2a);
                    float dist = __fmaf_rn(-2.0f, dA0, t);
                    if (dist < minv[2*rp]) { minv[2*rp] = dist; minj[2*rp] = (unsigned)code0; }
                    t = __fadd_rn(sz0, e2b);
                    dist = __fmaf_rn(-2.0f, dB0, t);
                    if (dist < minv[2*rp]) { minv[2*rp] = dist; minj[2*rp] = (unsigned)(code0 + 1); }
                    // row 2rp+1
                    t = __fadd_rn(sz1, e2a);
                    dist = __fmaf_rn(-2.0f, dA1, t);
                    if (dist < minv[2*rp+1]) { minv[2*rp+1] = dist; minj[2*rp+1] = (unsigned)code0; }
                    t = __fadd_rn(sz1, e2b);
                    dist = __fmaf_rn(-2.0f, dB1, t);
                    if (dist < minv[2*rp+1]) { minv[2*rp+1] = dist; minj[2*rp+1] = (unsigned)(code0 + 1); }
                }
            }
        }
    }

    // Cross-thread reduce: packed ordered-float | idx, atomicMin
    // (min picks lowest index on exact ties — reference tie-break).
    #pragma unroll
    for (int i = 0; i < 8; i++) {
        unsigned fb = __float_as_uint(minv[i]);
        fb = (fb & 0x80000000u) ? ~fb : (fb | 0x80000000u);
        unsigned long long p =
            ((unsigned long long)fb << 32) | (unsigned long long)minj[i];
        atomicMin(&rmin[ty * 8 + i], p);
    }
    __syncthreads();

    // Epilogue: 2 threads per row, 128 d's each.
    const int r = tid & 127;
    const int half = tid >> 7;
    const int n = nbase + r;
    const unsigned code = (unsigned)(rmin[r] & 0xFFFFFFFFu);
    if (half == 0) idxf[n] = (float)code;
    const float* erow = emb + (size_t)code * D_DIM;
    float* zqb = zq + (size_t)b * (D_DIM * HW) + hwbase;
    float* lrow = loss + (size_t)n * D_DIM;
    #pragma unroll 4
    for (int sft = 0; sft < D_DIM / 2; sft++) {
        const int d = half * (D_DIM / 2) + sft;
        float zv = zb[(size_t)d * HW + r];
        float ev = __ldg(&erow[d]);
        zqb[(size_t)d * HW + r] = ev;
        float df = __fadd_rn(ev, -zv);
        lrow[d] = __fmul_rn(df, df);
    }
}

extern "C" void kernel_launch(void* const* d_in, const int* in_sizes, int n_in,
                              void* d_out, int out_size) {
    const float* z   = (const float*)d_in[0];   // [32,256,32,32]
    const float* emb = (const float*)d_in[1];   // [1024,256]
    float* out = (float*)d_out;

    const int n_z = in_sizes[0];                // 8388608
    const int N = n_z / D_DIM;                  // 32768

    float* zq   = out;
    float* idxf = out + n_z;
    float* loss = out + n_z + N;

    vq_prep<<<K_CODES, D_DIM>>>(emb);
    vq_main<<<N / BM, 256>>>(z, emb, zq, idxf, loss);
}